// round 13
// baseline (speedup 1.0000x reference)
#include <cuda_runtime.h>
#include <cuda_fp16.h>
#include <cstdint>

#define B_ 8
#define D_ 128
#define N_ 2048
#define BM 128
#define BN 128
#define NITER (N_ / BN)

__device__ __forceinline__ uint32_t s2u(const void* p) {
    uint32_t a;
    asm("{ .reg .u64 t; cvta.to.shared.u64 t, %1; cvt.u32.u64 %0, t; }" : "=r"(a) : "l"(p));
    return a;
}

__device__ __forceinline__ void ldmx4(uint32_t* r, uint32_t addr) {
    asm volatile("ldmatrix.sync.aligned.m8n8.x4.shared.b16 {%0,%1,%2,%3}, [%4];"
        : "=r"(r[0]), "=r"(r[1]), "=r"(r[2]), "=r"(r[3]) : "r"(addr));
}
__device__ __forceinline__ void ldmx4t(uint32_t* r, uint32_t addr) {
    asm volatile("ldmatrix.sync.aligned.m8n8.x4.trans.shared.b16 {%0,%1,%2,%3}, [%4];"
        : "=r"(r[0]), "=r"(r[1]), "=r"(r[2]), "=r"(r[3]) : "r"(addr));
}
// f32-accumulate (MMA2: K-depth 2048 needs fp32)
__device__ __forceinline__ void mma16816(float* d, const uint32_t* a, const uint32_t* b) {
    asm volatile("mma.sync.aligned.m16n8k16.row.col.f32.f16.f16.f32 "
        "{%0,%1,%2,%3}, {%4,%5,%6,%7}, {%8,%9}, {%0,%1,%2,%3};"
        : "+f"(d[0]), "+f"(d[1]), "+f"(d[2]), "+f"(d[3])
        : "r"(a[0]), "r"(a[1]), "r"(a[2]), "r"(a[3]), "r"(b[0]), "r"(b[1]));
}
// f16-accumulate (MMA1: K-depth 128, scaled operands keep accumulator small)
__device__ __forceinline__ void mma16816h(uint32_t* d, const uint32_t* a, const uint32_t* b) {
    asm volatile("mma.sync.aligned.m16n8k16.row.col.f16.f16.f16.f16 "
        "{%0,%1}, {%2,%3,%4,%5}, {%6,%7}, {%0,%1};"
        : "+r"(d[0]), "+r"(d[1])
        : "r"(a[0]), "r"(a[1]), "r"(a[2]), "r"(a[3]), "r"(b[0]), "r"(b[1]));
}

// K is pre-scaled by 0.5/sqrt(128): sigmoid(S/sqrt(128)) = 0.5*tanh(x)+0.5
__device__ __forceinline__ float sigf(float x) {
    float t;
    asm("tanh.approx.f32 %0, %1;" : "=f"(t) : "f"(x));
    return fmaf(t, 0.5f, 0.5f);
}
__device__ __forceinline__ uint32_t packh2(float a, float b) {
    uint32_t r;
    asm("cvt.rn.f16x2.f32 %0, %1, %2;" : "=r"(r) : "f"(b), "f"(a));
    return r;
}
__device__ __forceinline__ float2 uph2(uint32_t u) {
    __half2 h = *reinterpret_cast<__half2*>(&u);
    return __half22float2(h);
}
__device__ __forceinline__ uint4 cvt8(float4 a, float4 b) {
    uint4 r;
    r.x = packh2(a.x, a.y); r.y = packh2(a.z, a.w);
    r.z = packh2(b.x, b.y); r.w = packh2(b.z, b.w);
    return r;
}

// smem: K 32KB @0 | Q[2] 64KB @32K | V[2] 64KB @96K
#define SM_K 0
#define SM_Q 32768
#define SM_V 98304
#define SMEM_TOTAL 163840

__global__ __launch_bounds__(256, 1)
void sigattn_hmma(const float* __restrict__ Q, const float* __restrict__ K,
                  const float* __restrict__ V, float* __restrict__ O) {
    extern __shared__ char sm[];
    const uint32_t sb = s2u(sm);
    const int tid = threadIdx.x, w = tid >> 5, lane = tid & 31;
    const int b = blockIdx.y, m0 = blockIdx.x * BM;
    const int g = lane >> 3, sx = lane & 7;

    // in-kernel fp32->fp16 loader for Q and V tiles (no prep kernel)
    auto loadQV = [&](int it, int buf) {
        const int n0 = it * BN;
#pragma unroll
        for (int r = 0; r < 8; r++) {
            int i = tid + r * 256;
            int d = i >> 4, c = i & 15;
            uint32_t off = (uint32_t)(d * 256 + ((c ^ (d & 7)) << 4));
            const float4* qs = (const float4*)(Q + (size_t)(b * D_ + d) * N_ + n0 + c * 8);
            const float4* vs = (const float4*)(V + (size_t)(b * D_ + d) * N_ + n0 + c * 8);
            float4 q0 = qs[0], q1 = qs[1];
            float4 v0 = vs[0], v1 = vs[1];
            *(uint4*)(sm + SM_Q + buf * 32768 + off) = cvt8(q0, q1);
            *(uint4*)(sm + SM_V + buf * 32768 + off) = cvt8(v0, v1);
        }
    };

    // prologue: K tile (scaled by 0.5/sqrt(128)) + (Q,V)(0)
    {
        const float C2 = 0.5f * 0.08838834764831845f;
#pragma unroll
        for (int r = 0; r < 8; r++) {
            int i = tid + r * 256;
            int d = i >> 4, c = i & 15;
            const float4* ks = (const float4*)(K + (size_t)(b * D_ + d) * N_ + m0 + c * 8);
            float4 k0 = ks[0], k1 = ks[1];
            k0.x *= C2; k0.y *= C2; k0.z *= C2; k0.w *= C2;
            k1.x *= C2; k1.y *= C2; k1.z *= C2; k1.w *= C2;
            *(uint4*)(sm + SM_K + (uint32_t)(d * 256 + ((c ^ (d & 7)) << 4))) = cvt8(k0, k1);
        }
    }
    loadQV(0, 0);
    __syncthreads();

    // ---- K frags (A m16k16, m-block = w) via ldmatrix.trans from [d][m] ----
    uint32_t kf[8][4];
    {
        const int drow = (g >> 1) * 8 + sx;
        const uint32_t coff = (uint32_t)((((2 * w + (g & 1)) ^ sx) & 15) << 4);
#pragma unroll
        for (int kc = 0; kc < 8; kc++)
            ldmx4t(kf[kc], sb + SM_K + (uint32_t)((kc * 16 + drow) * 256) + coff);
    }

    float ob[16][4];
#pragma unroll
    for (int i = 0; i < 16; i++)
#pragma unroll
        for (int j = 0; j < 4; j++) ob[i][j] = 0.0f;

    const int qrow  = (g & 1) * 8 + sx;   // Q trans-tile d-row offset
    const int qcoff = g >> 1;             // Q chunk parity
    const int rL    = sx + ((lane >> 4) << 3);  // V ldmatrix row
    const int cp_   = g & 1;              // V chunk parity

    for (int it = 0; it < NITER; it++) {
        const int buf = it & 1;
        if (it + 1 < NITER) loadQV(it + 1, buf ^ 1);

        const uint32_t qbuf = sb + SM_Q + buf * 32768;
        const uint32_t vbuf = sb + SM_V + buf * 32768;

        // MMA1 (f16 acc) on a 32-n chunk ci
        auto do_mma1 = [&](int ci, uint32_t (&sc)[4][2]) {
#pragma unroll
            for (int nj = 0; nj < 4; nj++) { sc[nj][0] = 0u; sc[nj][1] = 0u; }
#pragma unroll
            for (int kc = 0; kc < 8; kc++) {
                uint32_t qb8[8];
                const uint32_t qr = qbuf + (uint32_t)((kc * 16 + qrow) * 256);
                ldmx4t(&qb8[0], qr + (uint32_t)((((4 * ci + qcoff)     ^ sx) & 15) << 4));
                ldmx4t(&qb8[4], qr + (uint32_t)((((4 * ci + 2 + qcoff) ^ sx) & 15) << 4));
                mma16816h(sc[0], kf[kc], &qb8[0]);
                mma16816h(sc[1], kf[kc], &qb8[2]);
                mma16816h(sc[2], kf[kc], &qb8[4]);
                mma16816h(sc[3], kf[kc], &qb8[6]);
            }
        };
        // MMA2 (f32 acc) on chunk ci with P frags
        auto do_mma2 = [&](int ci, uint32_t (&p)[4][2]) {
#pragma unroll
            for (int kcl = 0; kcl < 2; kcl++) {
                const int cv = 4 * ci + 2 * kcl + cp_;
                const uint32_t swz = (uint32_t)(((cv ^ sx) & 15) << 4);
                uint32_t a[4] = { p[2 * kcl][0], p[2 * kcl][1],
                                  p[2 * kcl + 1][0], p[2 * kcl + 1][1] };
#pragma unroll
                for (int j = 0; j < 8; j++) {
                    uint32_t vb[4];
                    ldmx4(vb, vbuf + (uint32_t)(rL * 256 + j * 4096) + swz);
                    mma16816(ob[2 * j],     a, &vb[0]);
                    mma16816(ob[2 * j + 1], a, &vb[2]);
                }
            }
        };

        // pipelined chunks: MMA1(c+1) overlaps sig(c)+MMA2(c)
        uint32_t sc[2][4][2];
        do_mma1(0, sc[0]);
#pragma unroll
        for (int ci = 0; ci < 4; ci++) {
            if (ci < 3) do_mma1(ci + 1, sc[(ci + 1) & 1]);
            uint32_t p[4][2];
            uint32_t (&s)[4][2] = sc[ci & 1];
#pragma unroll
            for (int nj = 0; nj < 4; nj++) {
                float2 f0 = uph2(s[nj][0]);
                float2 f1 = uph2(s[nj][1]);
                p[nj][0] = packh2(sigf(f0.x), sigf(f0.y));
                p[nj][1] = packh2(sigf(f1.x), sigf(f1.y));
            }
            do_mma2(ci, p);
        }

        __syncthreads();
    }

    // ---- epilogue: O'[m,v] -> O[b][v][m0+m] ----
    float* Ob = O + (size_t)b * D_ * N_ + m0;
    const int r  = w * 16 + (lane >> 2);
    const int c0 = 2 * (lane & 3);
#pragma unroll
    for (int i = 0; i < 16; i++) {
        const int v = 8 * i + c0;
        Ob[(size_t)v * N_ + r]           = ob[i][0];
        Ob[(size_t)(v + 1) * N_ + r]     = ob[i][1];
        Ob[(size_t)v * N_ + r + 8]       = ob[i][2];
        Ob[(size_t)(v + 1) * N_ + r + 8] = ob[i][3];
    }
}

extern "C" void kernel_launch(void* const* d_in, const int* in_sizes, int n_in,
                              void* d_out, int out_size) {
    const float* Q = (const float*)d_in[0];
    const float* K = (const float*)d_in[1];
    const float* V = (const float*)d_in[2];
    float* O = (float*)d_out;

    cudaFuncSetAttribute(sigattn_hmma, cudaFuncAttributeMaxDynamicSharedMemorySize, SMEM_TOTAL);
    sigattn_hmma<<<dim3(N_ / BM, B_), 256, SMEM_TOTAL>>>(Q, K, V, O);
}

// round 14
// speedup vs baseline: 1.3804x; 1.3804x over previous
#include <cuda_runtime.h>
#include <cuda_fp16.h>
#include <cstdint>

#define B_ 8
#define D_ 128
#define N_ 2048
#define BM 128
#define BN 128
#define NITER (N_ / BN)

__device__ __align__(16) __half g_Qh[B_ * D_ * N_];  // [b][d][n]
__device__ __align__(16) __half g_Vh[B_ * D_ * N_];  // [b][v][n]

__device__ __forceinline__ uint32_t s2u(const void* p) {
    uint32_t a;
    asm("{ .reg .u64 t; cvta.to.shared.u64 t, %1; cvt.u32.u64 %0, t; }" : "=r"(a) : "l"(p));
    return a;
}

#define CPA16(dst, src) \
    asm volatile("cp.async.cg.shared.global [%0], [%1], 16;" :: "r"(dst), "l"(src))
#define CPA_COMMIT() asm volatile("cp.async.commit_group;" ::: "memory")
#define CPA_WAIT0()  asm volatile("cp.async.wait_group 0;" ::: "memory")

__device__ __forceinline__ void ldmx4(uint32_t* r, uint32_t addr) {
    asm volatile("ldmatrix.sync.aligned.m8n8.x4.shared.b16 {%0,%1,%2,%3}, [%4];"
        : "=r"(r[0]), "=r"(r[1]), "=r"(r[2]), "=r"(r[3]) : "r"(addr));
}
__device__ __forceinline__ void ldmx4t(uint32_t* r, uint32_t addr) {
    asm volatile("ldmatrix.sync.aligned.m8n8.x4.trans.shared.b16 {%0,%1,%2,%3}, [%4];"
        : "=r"(r[0]), "=r"(r[1]), "=r"(r[2]), "=r"(r[3]) : "r"(addr));
}
// f32-accumulate (MMA2: K-depth 2048 needs fp32)
__device__ __forceinline__ void mma16816(float* d, const uint32_t* a, const uint32_t* b) {
    asm volatile("mma.sync.aligned.m16n8k16.row.col.f32.f16.f16.f32 "
        "{%0,%1,%2,%3}, {%4,%5,%6,%7}, {%8,%9}, {%0,%1,%2,%3};"
        : "+f"(d[0]), "+f"(d[1]), "+f"(d[2]), "+f"(d[3])
        : "r"(a[0]), "r"(a[1]), "r"(a[2]), "r"(a[3]), "r"(b[0]), "r"(b[1]));
}
// f16-accumulate (MMA1: K-depth 128, pre-scaled operands keep accumulator small)
__device__ __forceinline__ void mma16816h(uint32_t* d, const uint32_t* a, const uint32_t* b) {
    asm volatile("mma.sync.aligned.m16n8k16.row.col.f16.f16.f16.f16 "
        "{%0,%1}, {%2,%3,%4,%5}, {%6,%7}, {%0,%1};"
        : "+r"(d[0]), "+r"(d[1])
        : "r"(a[0]), "r"(a[1]), "r"(a[2]), "r"(a[3]), "r"(b[0]), "r"(b[1]));
}

// K pre-scaled by 0.5/sqrt(128): sigmoid(S/sqrt(128)) = 0.5*tanh(x)+0.5
__device__ __forceinline__ float sigf(float x) {
    float t;
    asm("tanh.approx.f32 %0, %1;" : "=f"(t) : "f"(x));
    return fmaf(t, 0.5f, 0.5f);
}
__device__ __forceinline__ uint32_t packh2(float a, float b) {
    uint32_t r;
    asm("cvt.rn.f16x2.f32 %0, %1, %2;" : "=r"(r) : "f"(b), "f"(a));
    return r;
}
__device__ __forceinline__ float2 uph2(uint32_t u) {
    __half2 h = *reinterpret_cast<__half2*>(&u);
    return __half22float2(h);
}

// smem: K 32KB @0 | Q[2] 64KB @32K | V[2] 64KB @96K
#define SM_K 0
#define SM_Q 32768
#define SM_V 98304
#define SMEM_TOTAL 163840

__global__ __launch_bounds__(256, 1)
void sigattn_hmma(const float* __restrict__ Kf, float* __restrict__ O) {
    extern __shared__ char sm[];
    const uint32_t sb = s2u(sm);
    const int tid = threadIdx.x, w = tid >> 5, lane = tid & 31;
    const int b = blockIdx.y, m0 = blockIdx.x * BM;
    const int g = lane >> 3, sx = lane & 7;

    auto loadQV = [&](int it, int buf) {
        const int n0 = it * BN;
        const uint32_t qd = sb + SM_Q + buf * 32768;
        const uint32_t vd = sb + SM_V + buf * 32768;
#pragma unroll
        for (int r = 0; r < 8; r++) {
            int i = tid + r * 256;
            int d = i >> 4, c = i & 15;
            uint32_t off = (uint32_t)(d * 256 + ((c ^ (d & 7)) << 4));
            CPA16(qd + off, (const char*)g_Qh + ((size_t)(b * D_ + d) * N_ + n0 + c * 8) * 2);
            CPA16(vd + off, (const char*)g_Vh + ((size_t)(b * D_ + d) * N_ + n0 + c * 8) * 2);
        }
    };

    // prologue: Q,V(0) async; K tile converted in-kernel (one-time, scaled)
    loadQV(0, 0);
    CPA_COMMIT();
    {
        const float C2 = 0.5f * 0.08838834764831845f;
#pragma unroll
        for (int r = 0; r < 8; r++) {
            int i = tid + r * 256;
            int d = i >> 4, c = i & 15;
            const float4* ks = (const float4*)(Kf + (size_t)(b * D_ + d) * N_ + m0 + c * 8);
            float4 k0 = ks[0], k1 = ks[1];
            uint4 h;
            h.x = packh2(k0.x * C2, k0.y * C2);
            h.y = packh2(k0.z * C2, k0.w * C2);
            h.z = packh2(k1.x * C2, k1.y * C2);
            h.w = packh2(k1.z * C2, k1.w * C2);
            *(uint4*)(sm + SM_K + (uint32_t)(d * 256 + ((c ^ (d & 7)) << 4))) = h;
        }
    }
    CPA_WAIT0();
    __syncthreads();

    // ---- K frags (A m16k16, m-block = w) via ldmatrix.trans from [d][m] ----
    uint32_t kf[8][4];
    {
        const int drow = (g >> 1) * 8 + sx;
        const uint32_t coff = (uint32_t)((((2 * w + (g & 1)) ^ sx) & 15) << 4);
#pragma unroll
        for (int kc = 0; kc < 8; kc++)
            ldmx4t(kf[kc], sb + SM_K + (uint32_t)((kc * 16 + drow) * 256) + coff);
    }

    float ob[16][4];
#pragma unroll
    for (int i = 0; i < 16; i++)
#pragma unroll
        for (int j = 0; j < 4; j++) ob[i][j] = 0.0f;

    const int qrow  = (g & 1) * 8 + sx;   // Q trans-tile d-row offset
    const int qcoff = g >> 1;             // Q chunk parity
    const int rL    = sx + ((lane >> 4) << 3);  // V ldmatrix row
    const int cp_   = g & 1;              // V chunk parity

    for (int it = 0; it < NITER; it++) {
        const int buf = it & 1;
        if (it + 1 < NITER) { loadQV(it + 1, buf ^ 1); CPA_COMMIT(); }

        const uint32_t qbuf = sb + SM_Q + buf * 32768;
        const uint32_t vbuf = sb + SM_V + buf * 32768;

        // MMA1 (f16 acc) on a 32-n chunk ci
        auto do_mma1 = [&](int ci, uint32_t (&sc)[4][2]) {
#pragma unroll
            for (int nj = 0; nj < 4; nj++) { sc[nj][0] = 0u; sc[nj][1] = 0u; }
#pragma unroll
            for (int kc = 0; kc < 8; kc++) {
                uint32_t qb8[8];
                const uint32_t qr = qbuf + (uint32_t)((kc * 16 + qrow) * 256);
                ldmx4t(&qb8[0], qr + (uint32_t)((((4 * ci + qcoff)     ^ sx) & 15) << 4));
                ldmx4t(&qb8[4], qr + (uint32_t)((((4 * ci + 2 + qcoff) ^ sx) & 15) << 4));
                mma16816h(sc[0], kf[kc], &qb8[0]);
                mma16816h(sc[1], kf[kc], &qb8[2]);
                mma16816h(sc[2], kf[kc], &qb8[4]);
                mma16816h(sc[3], kf[kc], &qb8[6]);
            }
        };
        // MMA2 (f32 acc) on chunk ci with P frags
        auto do_mma2 = [&](int ci, uint32_t (&p)[4][2]) {
#pragma unroll
            for (int kcl = 0; kcl < 2; kcl++) {
                const int cv = 4 * ci + 2 * kcl + cp_;
                const uint32_t swz = (uint32_t)(((cv ^ sx) & 15) << 4);
                uint32_t a[4] = { p[2 * kcl][0], p[2 * kcl][1],
                                  p[2 * kcl + 1][0], p[2 * kcl + 1][1] };
#pragma unroll
                for (int j = 0; j < 8; j++) {
                    uint32_t vb[4];
                    ldmx4(vb, vbuf + (uint32_t)(rL * 256 + j * 4096) + swz);
                    mma16816(ob[2 * j],     a, &vb[0]);
                    mma16816(ob[2 * j + 1], a, &vb[2]);
                }
            }
        };

        // pipelined chunks: MMA1(c+1) overlaps sig(c)+MMA2(c)
        uint32_t sc[2][4][2];
        do_mma1(0, sc[0]);
#pragma unroll
        for (int ci = 0; ci < 4; ci++) {
            if (ci < 3) do_mma1(ci + 1, sc[(ci + 1) & 1]);
            uint32_t p[4][2];
            uint32_t (&s)[4][2] = sc[ci & 1];
#pragma unroll
            for (int nj = 0; nj < 4; nj++) {
                float2 f0 = uph2(s[nj][0]);
                float2 f1 = uph2(s[nj][1]);
                p[nj][0] = packh2(sigf(f0.x), sigf(f0.y));
                p[nj][1] = packh2(sigf(f1.x), sigf(f1.y));
            }
            do_mma2(ci, p);
        }

        CPA_WAIT0();
        __syncthreads();
    }

    // ---- epilogue: O'[m,v] -> O[b][v][m0+m] ----
    float* Ob = O + (size_t)b * D_ * N_ + m0;
    const int r  = w * 16 + (lane >> 2);
    const int c0 = 2 * (lane & 3);
#pragma unroll
    for (int i = 0; i < 16; i++) {
        const int v = 8 * i + c0;
        Ob[(size_t)v * N_ + r]           = ob[i][0];
        Ob[(size_t)(v + 1) * N_ + r]     = ob[i][1];
        Ob[(size_t)v * N_ + r + 8]       = ob[i][2];
        Ob[(size_t)(v + 1) * N_ + r + 8] = ob[i][3];
    }
}

// ---- preprocess: fp32 -> fp16 cast for Q and V only ----
__global__ void prep_cast(const float* __restrict__ Q, const float* __restrict__ V) {
    int i = blockIdx.x * 256 + threadIdx.x;
    const float* src = (blockIdx.y == 0) ? Q : V;
    __half* dst = (blockIdx.y == 0) ? g_Qh : g_Vh;
    float4 v = ((const float4*)src)[i];
    __half2* o = (__half2*)dst;
    o[2 * i]     = __floats2half2_rn(v.x, v.y);
    o[2 * i + 1] = __floats2half2_rn(v.z, v.w);
}

extern "C" void kernel_launch(void* const* d_in, const int* in_sizes, int n_in,
                              void* d_out, int out_size) {
    const float* Q = (const float*)d_in[0];
    const float* K = (const float*)d_in[1];
    const float* V = (const float*)d_in[2];
    float* O = (float*)d_out;

    prep_cast<<<dim3((B_ * D_ * N_ / 4) / 256, 2), 256>>>(Q, V);

    cudaFuncSetAttribute(sigattn_hmma, cudaFuncAttributeMaxDynamicSharedMemorySize, SMEM_TOTAL);
    sigattn_hmma<<<dim3(N_ / BM, B_), 256, SMEM_TOTAL>>>(K, O);
}